// round 1
// baseline (speedup 1.0000x reference)
#include <cuda_runtime.h>
#include <math.h>

// Problem constants
#define BB   4
#define LL   2048
#define DD   512
#define HH   8
#define DK   64
#define FFD  2048
#define NTOP 40
#define SK   40
#define BH   (BB*HH)     // 32
#define ROWS (BB*LL)     // 8192

// ---------------- scratch (device globals; no allocs allowed) ----------------
__device__ float g_Q[ROWS*DD];
__device__ float g_K[ROWS*DD];
__device__ float g_V[ROWS*DD];
__device__ float g_ctx[ROWS*DD];
__device__ float g_h1[ROWS*DD];
__device__ float g_t0[ROWS*DD];       // attn_out, later ff2 out
__device__ float g_ff[ROWS*FFD];      // gelu(ff1) intermediate
__device__ float g_M[BH*LL];
__device__ float g_vmean[BH*DK];
__device__ int   g_top[BH*NTOP];

// ---------------- packed f32x2 fma ----------------
__device__ __forceinline__ void ffma2(unsigned long long &d, unsigned long long a, unsigned long long b) {
    asm("fma.rn.f32x2 %0, %1, %2, %0;" : "+l"(d) : "l"(a), "l"(b));
}

// =====================================================================
// GEMM: C[M,N] = A[M,K] @ W[N,K]^T + bias, optional exact-GELU epilogue.
// BM=BN=128, BK=16, 256 threads, 8x8 per thread via FFMA2 pairs.
// A-tile stored DUPLICATED in smem (each value twice) so the a-operand of
// fma.rn.f32x2 is a single LDS.64; B read as adjacent-column LDS.64 pairs.
// =====================================================================
template<int ACT>
__global__ void __launch_bounds__(256, 2)
gemm_kernel(const float* __restrict__ A, const float* __restrict__ W,
            const float* __restrict__ bias, float* __restrict__ C,
            int M, int N, int K)
{
    constexpr int BM = 128, BN = 128, BK = 16;
    __shared__ __align__(16) float As[BK][2*BM];   // duplicated
    __shared__ __align__(16) float Bs[BK][BN];

    const int bm = blockIdx.y * BM;
    const int bn = blockIdx.x * BN;
    const int t  = threadIdx.x;
    const int tx = t & 15, ty = t >> 4;

    unsigned long long acc2[8][4];
    #pragma unroll
    for (int i = 0; i < 8; i++)
        #pragma unroll
        for (int j = 0; j < 4; j++) acc2[i][j] = 0ULL;

    for (int k0 = 0; k0 < K; k0 += BK) {
        #pragma unroll
        for (int u = 0; u < 2; u++) {
            int f = t + u * 256;            // float4 slot in [0,512)
            int r = f >> 2, c = (f & 3) << 2;
            float4 av = *reinterpret_cast<const float4*>(&A[(size_t)(bm + r) * K + k0 + c]);
            As[c+0][2*r] = av.x; As[c+0][2*r+1] = av.x;
            As[c+1][2*r] = av.y; As[c+1][2*r+1] = av.y;
            As[c+2][2*r] = av.z; As[c+2][2*r+1] = av.z;
            As[c+3][2*r] = av.w; As[c+3][2*r+1] = av.w;
            float4 bv = *reinterpret_cast<const float4*>(&W[(size_t)(bn + r) * K + k0 + c]);
            Bs[c+0][r] = bv.x; Bs[c+1][r] = bv.y; Bs[c+2][r] = bv.z; Bs[c+3][r] = bv.w;
        }
        __syncthreads();
        #pragma unroll
        for (int kk = 0; kk < BK; kk++) {
            unsigned long long a2[8], b2[4];
            #pragma unroll
            for (int i = 0; i < 8; i++)
                a2[i] = *reinterpret_cast<const unsigned long long*>(&As[kk][2*(ty + 16*i)]);
            #pragma unroll
            for (int j = 0; j < 4; j++)
                b2[j] = *reinterpret_cast<const unsigned long long*>(&Bs[kk][2*tx + 32*j]);
            #pragma unroll
            for (int i = 0; i < 8; i++)
                #pragma unroll
                for (int j = 0; j < 4; j++) ffma2(acc2[i][j], a2[i], b2[j]);
        }
        __syncthreads();
    }

    #pragma unroll
    for (int i = 0; i < 8; i++) {
        int row = bm + ty + 16*i;
        #pragma unroll
        for (int j = 0; j < 4; j++) {
            int col = bn + 2*tx + 32*j;
            float2 v;
            asm("mov.b64 {%0, %1}, %2;" : "=f"(v.x), "=f"(v.y) : "l"(acc2[i][j]));
            v.x += bias[col]; v.y += bias[col+1];
            if (ACT == 1) {
                v.x = 0.5f * v.x * (1.0f + erff(v.x * 0.70710678118654752440f));
                v.y = 0.5f * v.y * (1.0f + erff(v.y * 0.70710678118654752440f));
            }
            *reinterpret_cast<float2*>(&C[(size_t)row * N + col]) = v;
        }
    }
}

// =====================================================================
// Sample scores + sparsity measure M. One warp per (b,h,i):
// M[b,h,i] = max_j(q_i . k[idx[i,j]]) - sum_j(.)/L
// =====================================================================
__global__ void sample_scores_kernel(const int* __restrict__ idxs)
{
    int g    = blockIdx.x * 8 + (threadIdx.x >> 5);   // (bh, i) flat
    int lane = threadIdx.x & 31;
    int i  = g & (LL - 1);
    int bh = g >> 11;
    int b = bh >> 3, h = bh & 7;

    const float* qp = g_Q + (size_t)(b * LL + i) * DD + h * DK;
    float q0 = qp[lane], q1 = qp[32 + lane];

    float mx = -INFINITY, sm = 0.f;
    #pragma unroll 4
    for (int j = 0; j < SK; j++) {
        int kidx = idxs[i * SK + j];
        const float* kp = g_K + (size_t)(b * LL + kidx) * DD + h * DK;
        float s = q0 * kp[lane] + q1 * kp[32 + lane];
        #pragma unroll
        for (int off = 16; off; off >>= 1) s += __shfl_xor_sync(0xffffffffu, s, off);
        mx = fmaxf(mx, s);
        sm += s;
    }
    if (lane == 0) g_M[bh * LL + i] = mx - sm * (1.0f / LL);
}

// =====================================================================
// top-40 per (b,h): 40 passes of argmax (ties -> lowest index, matching
// jax.lax.top_k stability). One block per (b,h).
// =====================================================================
__global__ void topk_kernel()
{
    int bh = blockIdx.x;
    int t  = threadIdx.x;
    __shared__ float sv[LL];
    __shared__ float rv[256];
    __shared__ int   ri[256];

    for (int l = t; l < LL; l += 256) sv[l] = g_M[bh * LL + l];
    __syncthreads();

    for (int it = 0; it < NTOP; it++) {
        float bv = -INFINITY; int bi = LL;
        for (int l = t; l < LL; l += 256) {
            float v = sv[l];
            if (v > bv || (v == bv && l < bi)) { bv = v; bi = l; }
        }
        rv[t] = bv; ri[t] = bi;
        __syncthreads();
        for (int s = 128; s; s >>= 1) {
            if (t < s) {
                if (rv[t+s] > rv[t] || (rv[t+s] == rv[t] && ri[t+s] < ri[t])) {
                    rv[t] = rv[t+s]; ri[t] = ri[t+s];
                }
            }
            __syncthreads();
        }
        if (t == 0) { g_top[bh * NTOP + it] = ri[0]; sv[ri[0]] = -INFINITY; }
        __syncthreads();
    }
}

// =====================================================================
// v-mean per (b,h): lazy-row context is uniform attention = mean(V).
// =====================================================================
__global__ void vmean_kernel()
{
    int bh = blockIdx.x; int b = bh >> 3, h = bh & 7;
    int t = threadIdx.x; int d = t & 63; int r0 = t >> 6;
    float s = 0.f;
    for (int l = r0; l < LL; l += 4)
        s += g_V[(size_t)(b * LL + l) * DD + h * DK + d];
    __shared__ float red[256];
    red[t] = s; __syncthreads();
    if (t < 64)
        g_vmean[bh * DK + t] = (red[t] + red[t+64] + red[t+128] + red[t+192]) * (1.0f / LL);
}

// Broadcast vmean into every ctx row (selected rows overwritten later).
__global__ void ctx_bcast_kernel()
{
    int idx = blockIdx.x * 256 + threadIdx.x;       // over ROWS*DD
    int row = idx >> 9;          // /512
    int col = idx & 511;
    int b = row >> 11;           // /2048
    int h = col >> 6;
    g_ctx[idx] = g_vmean[(b * HH + h) * DK + (col & 63)];
}

// =====================================================================
// Real attention for the 40 selected queries per (b,h).
// Block = (n, bh). Full-row softmax over 2048 keys, then p @ V.
// K/V tiles staged through smem (pad 65 -> conflict-free).
// =====================================================================
__global__ void attn_sel_kernel()
{
    int n = blockIdx.x, bh = blockIdx.y;
    int b = bh >> 3, h = bh & 7;
    int qi = g_top[bh * NTOP + n];
    int t = threadIdx.x;

    __shared__ float q[64];
    __shared__ float sc[LL];
    __shared__ __align__(16) float Ks[128][65];
    __shared__ float red[256];

    const size_t base = (size_t)b * LL * DD + h * DK;
    if (t < 64) q[t] = g_Q[base + (size_t)qi * DD + t];
    __syncthreads();

    // scores
    for (int kt = 0; kt < LL / 128; kt++) {
        #pragma unroll
        for (int u = 0; u < 8; u++) {
            int f = t + u * 256;                 // float4 slot in [0,2048)
            int r = f >> 4, c = (f & 15) << 2;
            float4 kv = *reinterpret_cast<const float4*>(&g_K[base + (size_t)(kt*128 + r) * DD + c]);
            Ks[r][c] = kv.x; Ks[r][c+1] = kv.y; Ks[r][c+2] = kv.z; Ks[r][c+3] = kv.w;
        }
        __syncthreads();
        if (t < 128) {
            float s = 0.f;
            #pragma unroll
            for (int k = 0; k < 64; k++) s += q[k] * Ks[t][k];
            sc[kt * 128 + t] = s;
        }
        __syncthreads();
    }

    // softmax
    float mx = -INFINITY;
    for (int l = t; l < LL; l += 256) mx = fmaxf(mx, sc[l]);
    red[t] = mx; __syncthreads();
    for (int s = 128; s; s >>= 1) { if (t < s) red[t] = fmaxf(red[t], red[t+s]); __syncthreads(); }
    mx = red[0]; __syncthreads();

    float sum = 0.f;
    for (int l = t; l < LL; l += 256) { float e = expf(sc[l] - mx); sc[l] = e; sum += e; }
    red[t] = sum; __syncthreads();
    for (int s = 128; s; s >>= 1) { if (t < s) red[t] += red[t+s]; __syncthreads(); }
    float inv = 1.0f / red[0];
    __syncthreads();

    // p @ V
    int d = t & 63, r0 = t >> 6;
    float acc = 0.f;
    for (int kt = 0; kt < LL / 128; kt++) {
        #pragma unroll
        for (int u = 0; u < 8; u++) {
            int f = t + u * 256;
            int r = f >> 4, c = (f & 15) << 2;
            float4 vv = *reinterpret_cast<const float4*>(&g_V[base + (size_t)(kt*128 + r) * DD + c]);
            Ks[r][c] = vv.x; Ks[r][c+1] = vv.y; Ks[r][c+2] = vv.z; Ks[r][c+3] = vv.w;
        }
        __syncthreads();
        #pragma unroll
        for (int rr = r0; rr < 128; rr += 4) acc += sc[kt * 128 + rr] * Ks[rr][d];
        __syncthreads();
    }
    red[t] = acc; __syncthreads();
    if (t < 64) {
        float c = (red[t] + red[t+64] + red[t+128] + red[t+192]) * inv;
        g_ctx[base + (size_t)qi * DD + t] = c;
    }
}

// =====================================================================
// out = LayerNorm(X + Y) * g + be   (row length 512, 128 thr x float4)
// =====================================================================
__global__ void ln_add_kernel(const float* __restrict__ X, const float* __restrict__ Y,
                              const float* __restrict__ gg, const float* __restrict__ be,
                              float* __restrict__ out)
{
    int row = blockIdx.x;
    int t = threadIdx.x;
    const float4* x4 = reinterpret_cast<const float4*>(X + (size_t)row * DD);
    const float4* y4 = reinterpret_cast<const float4*>(Y + (size_t)row * DD);
    float4 a = x4[t], bq = y4[t];
    float4 v = make_float4(a.x + bq.x, a.y + bq.y, a.z + bq.z, a.w + bq.w);

    float s  = v.x + v.y + v.z + v.w;
    float ss = v.x*v.x + v.y*v.y + v.z*v.z + v.w*v.w;
    __shared__ float rs[128], rq[128];
    rs[t] = s; rq[t] = ss; __syncthreads();
    for (int k = 64; k; k >>= 1) {
        if (t < k) { rs[t] += rs[t+k]; rq[t] += rq[t+k]; }
        __syncthreads();
    }
    float mean = rs[0] * (1.0f / DD);
    float var  = rq[0] * (1.0f / DD) - mean * mean;
    float rstd = rsqrtf(var + 1e-5f);

    float4 g4  = reinterpret_cast<const float4*>(gg)[t];
    float4 b4  = reinterpret_cast<const float4*>(be)[t];
    float4 o;
    o.x = (v.x - mean) * rstd * g4.x + b4.x;
    o.y = (v.y - mean) * rstd * g4.y + b4.y;
    o.z = (v.z - mean) * rstd * g4.z + b4.z;
    o.w = (v.w - mean) * rstd * g4.w + b4.w;
    reinterpret_cast<float4*>(out + (size_t)row * DD)[t] = o;
}

// =====================================================================
extern "C" void kernel_launch(void* const* d_in, const int* in_sizes, int n_in,
                              void* d_out, int out_size)
{
    const float* x    = (const float*)d_in[0];
    const int*   idxs = (const int*)  d_in[1];
    const float* Wq = (const float*)d_in[2];  const float* bq = (const float*)d_in[3];
    const float* Wk = (const float*)d_in[4];  const float* bk = (const float*)d_in[5];
    const float* Wv = (const float*)d_in[6];  const float* bv = (const float*)d_in[7];
    const float* Wo = (const float*)d_in[8];  const float* bo = (const float*)d_in[9];
    const float* W1 = (const float*)d_in[10]; const float* b1 = (const float*)d_in[11];
    const float* W2 = (const float*)d_in[12]; const float* b2 = (const float*)d_in[13];
    const float* g1 = (const float*)d_in[14]; const float* be1 = (const float*)d_in[15];
    const float* g2 = (const float*)d_in[16]; const float* be2 = (const float*)d_in[17];
    float* out = (float*)d_out;

    float *Q, *K, *V, *CTX, *H1, *T0, *FB;
    cudaGetSymbolAddress((void**)&Q,   g_Q);
    cudaGetSymbolAddress((void**)&K,   g_K);
    cudaGetSymbolAddress((void**)&V,   g_V);
    cudaGetSymbolAddress((void**)&CTX, g_ctx);
    cudaGetSymbolAddress((void**)&H1,  g_h1);
    cudaGetSymbolAddress((void**)&T0,  g_t0);
    cudaGetSymbolAddress((void**)&FB,  g_ff);

    dim3 gD(DD / 128, ROWS / 128);    // N=512 GEMMs
    dim3 gF(FFD / 128, ROWS / 128);   // N=2048 GEMM

    gemm_kernel<0><<<gD, 256>>>(x, Wq, bq, Q, ROWS, DD, DD);
    gemm_kernel<0><<<gD, 256>>>(x, Wk, bk, K, ROWS, DD, DD);
    gemm_kernel<0><<<gD, 256>>>(x, Wv, bv, V, ROWS, DD, DD);

    sample_scores_kernel<<<ROWS * HH / 8, 256>>>(idxs);
    topk_kernel<<<BH, 256>>>();
    vmean_kernel<<<BH, 256>>>();
    ctx_bcast_kernel<<<ROWS * DD / 256, 256>>>();
    attn_sel_kernel<<<dim3(NTOP, BH), 256>>>();

    gemm_kernel<0><<<gD, 256>>>(CTX, Wo, bo, T0, ROWS, DD, DD);
    ln_add_kernel<<<ROWS, 128>>>(x, T0, g1, be1, H1);

    gemm_kernel<1><<<gF, 256>>>(H1, W1, b1, FB, ROWS, FFD, DD);
    gemm_kernel<0><<<gD, 256>>>(FB, W2, b2, T0, ROWS, DD, FFD);
    ln_add_kernel<<<ROWS, 128>>>(H1, T0, g2, be2, out);
}

// round 4
// speedup vs baseline: 1.8997x; 1.8997x over previous
#include <cuda_runtime.h>
#include <cuda_bf16.h>
#include <math.h>
#include <stdint.h>

#define BB 4
#define LL 2048
#define DD 512
#define HH 8
#define DK 64
#define FFD 2048
#define NTOP 40
#define SK 40
#define BH (BB*HH)
#define ROWS (BB*LL)

__device__ float g_Q[ROWS*DD];
__device__ float g_K[ROWS*DD];
__device__ float g_V[ROWS*DD];
__device__ float g_ctx[ROWS*DD];
__device__ float g_h1[ROWS*DD];
__device__ float g_t0[ROWS*DD];
__device__ float g_M[BH*LL];
__device__ float g_vmean[BH*DK];
__device__ int   g_top[BH*NTOP];
__device__ __nv_bfloat16 g_Ahi[ROWS*DD];
__device__ __nv_bfloat16 g_Alo[ROWS*DD];
__device__ __nv_bfloat16 g_FFhi[ROWS*FFD];
__device__ __nv_bfloat16 g_FFlo[ROWS*FFD];
__device__ __nv_bfloat16 g_Whi[3*FFD*DD];
__device__ __nv_bfloat16 g_Wlo[3*FFD*DD];

__device__ __forceinline__ uint32_t smem_u32(const void* p){
    uint32_t a; asm("{ .reg .u64 t; cvta.to.shared.u64 t, %1; cvt.u32.u64 %0, t; }":"=r"(a):"l"(p)); return a;
}
__device__ __forceinline__ void cpasync16(uint32_t dst, const void* src){
    asm volatile("cp.async.cg.shared.global [%0], [%1], 16;" :: "r"(dst), "l"(src));
}
__device__ __forceinline__ void ldsm4(uint32_t* r, uint32_t addr){
    asm volatile("ldmatrix.sync.aligned.m8n8.x4.shared.b16 {%0,%1,%2,%3}, [%4];"
        : "=r"(r[0]),"=r"(r[1]),"=r"(r[2]),"=r"(r[3]) : "r"(addr));
}
__device__ __forceinline__ void mma_bf16(float* c, const uint32_t* a, const uint32_t* b){
    asm volatile("mma.sync.aligned.m16n8k16.row.col.f32.bf16.bf16.f32 "
        "{%0,%1,%2,%3}, {%4,%5,%6,%7}, {%8,%9}, {%0,%1,%2,%3};"
        : "+f"(c[0]),"+f"(c[1]),"+f"(c[2]),"+f"(c[3])
        : "r"(a[0]),"r"(a[1]),"r"(a[2]),"r"(a[3]),"r"(b[0]),"r"(b[1]));
}
__device__ __forceinline__ void split2(float v, __nv_bfloat16& h, __nv_bfloat16& l){
    h = __float2bfloat16(v);
    l = __float2bfloat16(v - __bfloat162float(h));
}

// =====================================================================
// HMMA GEMM: C[M,N] = A[M,K] @ W[N,K]^T + bias. bf16 hi/lo 3-term split,
// fp32 accumulators. BM=BN=128, BK=32, 256 thr (8 warps, 2Mx4N),
// warp tile 64x32 = 4x4 m16n8k16 tiles. cp.async double buffer.
// Tile rows padded to 80B (stride 40 bf16): conflict-free ldmatrix/LDS.
// Stage layout: Ah(10240) | Al | Bh | Bl = 40960B; 2 stages = 81920B.
// =====================================================================
template<int ACT, int SPLIT>
__global__ void __launch_bounds__(256,1)
gemm_hmma(const __nv_bfloat16* __restrict__ Ahi, const __nv_bfloat16* __restrict__ Alo,
          const __nv_bfloat16* __restrict__ Bhi, const __nv_bfloat16* __restrict__ Blo,
          const float* __restrict__ bias, float* __restrict__ C,
          __nv_bfloat16* __restrict__ Chi, __nv_bfloat16* __restrict__ Clo,
          int K, int ldc)
{
    extern __shared__ __align__(16) char sm[];
    const int t = threadIdx.x, lane = t&31, w = t>>5;
    const int wm = w>>2, wn = w&3;
    const int bm = blockIdx.y*128, bn = blockIdx.x*128;
    const int group = lane>>2, tig = lane&3;
    const uint32_t sbase = smem_u32(sm);

    float acc[4][4][4];
    #pragma unroll
    for (int i=0;i<4;i++)
        #pragma unroll
        for (int j=0;j<4;j++)
            #pragma unroll
            for (int r=0;r<4;r++) acc[i][j][r]=0.f;

    const __nv_bfloat16* srcs[4] = {Ahi, Alo, Bhi, Blo};

    const int nch = K>>5;
    // prologue load stage 0
    {
        #pragma unroll
        for (int u=0; u<8; u++){
            int q = t + u*256;
            int tile = q>>9, rem = q&511;
            int r = rem>>2, c = rem&3;
            const __nv_bfloat16* src = srcs[tile] + (size_t)(((tile<2)?bm:bn) + r)*K + c*8;
            cpasync16(sbase + tile*10240 + r*80 + c*16, src);
        }
        asm volatile("cp.async.commit_group;");
    }

    for (int ch=0; ch<nch; ch++){
        asm volatile("cp.async.wait_group 0;");
        __syncthreads();
        if (ch+1 < nch){
            const int k0 = (ch+1)<<5;
            const uint32_t dst0 = sbase + ((ch+1)&1)*40960;
            #pragma unroll
            for (int u=0; u<8; u++){
                int q = t + u*256;
                int tile = q>>9, rem = q&511;
                int r = rem>>2, c = rem&3;
                const __nv_bfloat16* src = srcs[tile] + (size_t)(((tile<2)?bm:bn) + r)*K + k0 + c*8;
                cpasync16(dst0 + tile*10240 + r*80 + c*16, src);
            }
            asm volatile("cp.async.commit_group;");
        }
        const uint32_t stg = sbase + (ch&1)*40960;
        const char* stgp = sm + (ch&1)*40960;
        #pragma unroll
        for (int kk=0; kk<2; kk++){
            uint32_t a_h[4][4], a_l[4][4], b_h[4][2], b_l[4][2];
            #pragma unroll
            for (int mt=0; mt<4; mt++){
                uint32_t ra = stg + (uint32_t)((wm*64 + mt*16 + (lane&15))*80 + (lane>>4)*16 + kk*32);
                ldsm4(a_h[mt], ra);
                ldsm4(a_l[mt], ra + 10240u);
            }
            #pragma unroll
            for (int nt=0; nt<4; nt++){
                int off = 20480 + (wn*32 + nt*8 + group)*80 + tig*4 + kk*32;
                b_h[nt][0] = *(const uint32_t*)(stgp + off);
                b_h[nt][1] = *(const uint32_t*)(stgp + off + 16);
                b_l[nt][0] = *(const uint32_t*)(stgp + off + 10240);
                b_l[nt][1] = *(const uint32_t*)(stgp + off + 10240 + 16);
            }
            #pragma unroll
            for (int mt=0; mt<4; mt++)
                #pragma unroll
                for (int nt=0; nt<4; nt++){
                    mma_bf16(acc[mt][nt], a_h[mt], b_h[nt]);
                    mma_bf16(acc[mt][nt], a_h[mt], b_l[nt]);
                    mma_bf16(acc[mt][nt], a_l[mt], b_h[nt]);
                }
        }
    }
    __syncthreads();

    // epilogue
    #pragma unroll
    for (int mt=0; mt<4; mt++){
        #pragma unroll
        for (int nt=0; nt<4; nt++){
            int r0  = bm + wm*64 + mt*16 + group;
            int col = bn + wn*32 + nt*8 + tig*2;
            float bb0 = bias[col], bb1 = bias[col+1];
            #pragma unroll
            for (int hh2=0; hh2<2; hh2++){
                int row = r0 + hh2*8;
                float v0 = acc[mt][nt][hh2*2+0] + bb0;
                float v1 = acc[mt][nt][hh2*2+1] + bb1;
                if (ACT==1){
                    v0 = 0.5f*v0*(1.0f + erff(v0*0.70710678118654752440f));
                    v1 = 0.5f*v1*(1.0f + erff(v1*0.70710678118654752440f));
                }
                if (SPLIT==0){
                    *(float2*)(C + (size_t)row*ldc + col) = make_float2(v0, v1);
                } else {
                    __nv_bfloat16 h0,h1,l0,l1;
                    split2(v0,h0,l0); split2(v1,h1,l1);
                    uint32_t hw = (uint32_t)__bfloat16_as_ushort(h0) | ((uint32_t)__bfloat16_as_ushort(h1)<<16);
                    uint32_t lw = (uint32_t)__bfloat16_as_ushort(l0) | ((uint32_t)__bfloat16_as_ushort(l1)<<16);
                    *(uint32_t*)(Chi + (size_t)row*ldc + col) = hw;
                    *(uint32_t*)(Clo + (size_t)row*ldc + col) = lw;
                }
            }
        }
    }
}

__global__ void convert_split(const float* __restrict__ src,
                              __nv_bfloat16* __restrict__ hi, __nv_bfloat16* __restrict__ lo, int n4)
{
    int i = blockIdx.x*256 + threadIdx.x;
    if (i>=n4) return;
    float4 v = ((const float4*)src)[i];
    __nv_bfloat16 h0,h1,h2,h3,l0,l1,l2,l3;
    split2(v.x,h0,l0); split2(v.y,h1,l1); split2(v.z,h2,l2); split2(v.w,h3,l3);
    uint2 hw, lw;
    hw.x=(uint32_t)__bfloat16_as_ushort(h0)|((uint32_t)__bfloat16_as_ushort(h1)<<16);
    hw.y=(uint32_t)__bfloat16_as_ushort(h2)|((uint32_t)__bfloat16_as_ushort(h3)<<16);
    lw.x=(uint32_t)__bfloat16_as_ushort(l0)|((uint32_t)__bfloat16_as_ushort(l1)<<16);
    lw.y=(uint32_t)__bfloat16_as_ushort(l2)|((uint32_t)__bfloat16_as_ushort(l3)<<16);
    ((uint2*)hi)[i]=hw; ((uint2*)lo)[i]=lw;
}

__global__ void sample_scores_kernel(const int* __restrict__ idxs)
{
    int g = blockIdx.x*8 + (threadIdx.x>>5);
    int lane = threadIdx.x&31;
    int i = g&(LL-1), bh = g>>11, b = bh>>3, h = bh&7;
    const float* qp = g_Q + (size_t)(b*LL+i)*DD + h*DK;
    float q0 = qp[lane], q1 = qp[32+lane];
    float mx = -INFINITY, sm = 0.f;
    #pragma unroll 4
    for (int j=0; j<SK; j++){
        int kidx = idxs[i*SK+j];
        const float* kp = g_K + (size_t)(b*LL+kidx)*DD + h*DK;
        float s = q0*kp[lane] + q1*kp[32+lane];
        #pragma unroll
        for (int off=16; off; off>>=1) s += __shfl_xor_sync(0xffffffffu, s, off);
        mx = fmaxf(mx, s); sm += s;
    }
    if (lane==0) g_M[bh*LL+i] = mx - sm*(1.0f/LL);
}

__global__ void topk_kernel()
{
    int bh = blockIdx.x, t = threadIdx.x;
    __shared__ float sv[LL];
    __shared__ float rv[256];
    __shared__ int ri[256];
    for (int l=t; l<LL; l+=256) sv[l] = g_M[bh*LL+l];
    __syncthreads();
    for (int it=0; it<NTOP; it++){
        float bv = -INFINITY; int bi = LL;
        for (int l=t; l<LL; l+=256){
            float v = sv[l];
            if (v>bv || (v==bv && l<bi)){ bv=v; bi=l; }
        }
        rv[t]=bv; ri[t]=bi; __syncthreads();
        for (int s=128; s; s>>=1){
            if (t<s && (rv[t+s]>rv[t] || (rv[t+s]==rv[t] && ri[t+s]<ri[t]))){ rv[t]=rv[t+s]; ri[t]=ri[t+s]; }
            __syncthreads();
        }
        if (t==0){ g_top[bh*NTOP+it]=ri[0]; sv[ri[0]]=-INFINITY; }
        __syncthreads();
    }
}

__global__ void vmean_kernel()
{
    int bh = blockIdx.x, b = bh>>3, h = bh&7;
    int t = threadIdx.x, d = t&63, r0 = t>>6;
    float s = 0.f;
    for (int l=r0; l<LL; l+=4) s += g_V[(size_t)(b*LL+l)*DD + h*DK + d];
    __shared__ float red[256];
    red[t]=s; __syncthreads();
    if (t<64) g_vmean[bh*DK+t] = (red[t]+red[t+64]+red[t+128]+red[t+192])*(1.0f/LL);
}

__global__ void ctx_bcast_kernel()
{
    int idx = blockIdx.x*256 + threadIdx.x;
    int row = idx>>9, col = idx&511, b = row>>11, h = col>>6;
    g_ctx[idx] = g_vmean[(b*HH+h)*DK + (col&63)];
}

__global__ void attn_sel_kernel()
{
    int n = blockIdx.x, bh = blockIdx.y, b = bh>>3, h = bh&7;
    int qi = g_top[bh*NTOP+n];
    int t = threadIdx.x;
    __shared__ float q[64];
    __shared__ float sc[LL];
    __shared__ __align__(16) float Ks[128][65];
    __shared__ float red[256];
    const size_t base = (size_t)b*LL*DD + h*DK;
    if (t<64) q[t] = g_Q[base + (size_t)qi*DD + t];
    __syncthreads();
    for (int kt=0; kt<LL/128; kt++){
        #pragma unroll
        for (int u=0; u<8; u++){
            int f = t+u*256, r = f>>4, c = (f&15)<<2;
            float4 kv = *(const float4*)(&g_K[base + (size_t)(kt*128+r)*DD + c]);
            Ks[r][c]=kv.x; Ks[r][c+1]=kv.y; Ks[r][c+2]=kv.z; Ks[r][c+3]=kv.w;
        }
        __syncthreads();
        if (t<128){
            float s = 0.f;
            #pragma unroll
            for (int k=0; k<64; k++) s += q[k]*Ks[t][k];
            sc[kt*128+t] = s;
        }
        __syncthreads();
    }
    float mx = -INFINITY;
    for (int l=t; l<LL; l+=256) mx = fmaxf(mx, sc[l]);
    red[t]=mx; __syncthreads();
    for (int s=128; s; s>>=1){ if (t<s) red[t]=fmaxf(red[t],red[t+s]); __syncthreads(); }
    mx = red[0]; __syncthreads();
    float sum = 0.f;
    for (int l=t; l<LL; l+=256){ float e = expf(sc[l]-mx); sc[l]=e; sum+=e; }
    red[t]=sum; __syncthreads();
    for (int s=128; s; s>>=1){ if (t<s) red[t]+=red[t+s]; __syncthreads(); }
    float inv = 1.0f/red[0]; __syncthreads();
    int d = t&63, r0 = t>>6;
    float acc = 0.f;
    for (int kt=0; kt<LL/128; kt++){
        #pragma unroll
        for (int u=0; u<8; u++){
            int f = t+u*256, r = f>>4, c = (f&15)<<2;
            float4 vv = *(const float4*)(&g_V[base + (size_t)(kt*128+r)*DD + c]);
            Ks[r][c]=vv.x; Ks[r][c+1]=vv.y; Ks[r][c+2]=vv.z; Ks[r][c+3]=vv.w;
        }
        __syncthreads();
        #pragma unroll
        for (int rr=r0; rr<128; rr+=4) acc += sc[kt*128+rr]*Ks[rr][d];
        __syncthreads();
    }
    red[t]=acc; __syncthreads();
    if (t<64) g_ctx[base + (size_t)qi*DD + t] = (red[t]+red[t+64]+red[t+128]+red[t+192])*inv;
}

__global__ void ln_add_kernel(const float* __restrict__ X, const float* __restrict__ Y,
                              const float* __restrict__ gg, const float* __restrict__ be,
                              float* __restrict__ out)
{
    int row = blockIdx.x, t = threadIdx.x;
    float4 a = ((const float4*)(X + (size_t)row*DD))[t];
    float4 bq = ((const float4*)(Y + (size_t)row*DD))[t];
    float4 v = make_float4(a.x+bq.x, a.y+bq.y, a.z+bq.z, a.w+bq.w);
    float s = v.x+v.y+v.z+v.w;
    float ss = v.x*v.x+v.y*v.y+v.z*v.z+v.w*v.w;
    __shared__ float rs[128], rq[128];
    rs[t]=s; rq[t]=ss; __syncthreads();
    for (int k=64; k; k>>=1){ if (t<k){ rs[t]+=rs[t+k]; rq[t]+=rq[t+k]; } __syncthreads(); }
    float mean = rs[0]*(1.0f/DD);
    float var  = rq[0]*(1.0f/DD) - mean*mean;
    float rstd = rsqrtf(var + 1e-5f);
    float4 g4 = ((const float4*)gg)[t], b4 = ((const float4*)be)[t];
    float4 o;
    o.x=(v.x-mean)*rstd*g4.x+b4.x; o.y=(v.y-mean)*rstd*g4.y+b4.y;
    o.z=(v.z-mean)*rstd*g4.z+b4.z; o.w=(v.w-mean)*rstd*g4.w+b4.w;
    ((float4*)(out + (size_t)row*DD))[t] = o;
}

extern "C" void kernel_launch(void* const* d_in, const int* in_sizes, int n_in,
                              void* d_out, int out_size)
{
    const float* x    = (const float*)d_in[0];
    const int*   idxs = (const int*)  d_in[1];
    const float* Wq = (const float*)d_in[2];  const float* bq = (const float*)d_in[3];
    const float* Wk = (const float*)d_in[4];  const float* bk = (const float*)d_in[5];
    const float* Wv = (const float*)d_in[6];  const float* bv = (const float*)d_in[7];
    const float* Wo = (const float*)d_in[8];  const float* bo = (const float*)d_in[9];
    const float* W1 = (const float*)d_in[10]; const float* b1 = (const float*)d_in[11];
    const float* W2 = (const float*)d_in[12]; const float* b2 = (const float*)d_in[13];
    const float* g1 = (const float*)d_in[14]; const float* be1 = (const float*)d_in[15];
    const float* g2 = (const float*)d_in[16]; const float* be2 = (const float*)d_in[17];
    float* out = (float*)d_out;

    float *Q,*K,*V,*CTX,*H1,*T0;
    __nv_bfloat16 *AH,*AL,*FH,*FL,*WH,*WL;
    cudaGetSymbolAddress((void**)&Q, g_Q);   cudaGetSymbolAddress((void**)&K, g_K);
    cudaGetSymbolAddress((void**)&V, g_V);   cudaGetSymbolAddress((void**)&CTX, g_ctx);
    cudaGetSymbolAddress((void**)&H1, g_h1); cudaGetSymbolAddress((void**)&T0, g_t0);
    cudaGetSymbolAddress((void**)&AH, g_Ahi); cudaGetSymbolAddress((void**)&AL, g_Alo);
    cudaGetSymbolAddress((void**)&FH, g_FFhi); cudaGetSymbolAddress((void**)&FL, g_FFlo);
    cudaGetSymbolAddress((void**)&WH, g_Whi); cudaGetSymbolAddress((void**)&WL, g_Wlo);

    const int SMEM = 81920;
    cudaFuncSetAttribute(gemm_hmma<0,0>, cudaFuncAttributeMaxDynamicSharedMemorySize, SMEM);
    cudaFuncSetAttribute(gemm_hmma<1,1>, cudaFuncAttributeMaxDynamicSharedMemorySize, SMEM);

    const int DW = DD*DD;   // 262144
    convert_split<<<DW/1024, 256>>>(Wq, WH+0*DW, WL+0*DW, DW/4);
    convert_split<<<DW/1024, 256>>>(Wk, WH+1*DW, WL+1*DW, DW/4);
    convert_split<<<DW/1024, 256>>>(Wv, WH+2*DW, WL+2*DW, DW/4);
    convert_split<<<DW/1024, 256>>>(Wo, WH+3*DW, WL+3*DW, DW/4);
    convert_split<<<DW*4/1024, 256>>>(W1, WH+4*DW, WL+4*DW, DW);
    convert_split<<<DW*4/1024, 256>>>(W2, WH+8*DW, WL+8*DW, DW);
    convert_split<<<ROWS*DD/1024, 256>>>(x, AH, AL, ROWS*DD/4);

    dim3 gD(DD/128, ROWS/128), gF(FFD/128, ROWS/128);
    gemm_hmma<0,0><<<gD, 256, SMEM>>>(AH, AL, WH+0*DW, WL+0*DW, bq, Q, 0, 0, DD, DD);
    gemm_hmma<0,0><<<gD, 256, SMEM>>>(AH, AL, WH+1*DW, WL+1*DW, bk, K, 0, 0, DD, DD);
    gemm_hmma<0,0><<<gD, 256, SMEM>>>(AH, AL, WH+2*DW, WL+2*DW, bv, V, 0, 0, DD, DD);

    sample_scores_kernel<<<ROWS*HH/8, 256>>>(idxs);
    topk_kernel<<<BH, 256>>>();
    vmean_kernel<<<BH, 256>>>();
    ctx_bcast_kernel<<<ROWS*DD/256, 256>>>();
    attn_sel_kernel<<<dim3(NTOP, BH), 256>>>();

    convert_split<<<ROWS*DD/1024, 256>>>(CTX, AH, AL, ROWS*DD/4);
    gemm_hmma<0,0><<<gD, 256, SMEM>>>(AH, AL, WH+3*DW, WL+3*DW, bo, T0, 0, 0, DD, DD);
    ln_add_kernel<<<ROWS, 128>>>(x, T0, g1, be1, H1);

    convert_split<<<ROWS*DD/1024, 256>>>(H1, AH, AL, ROWS*DD/4);
    gemm_hmma<1,1><<<gF, 256, SMEM>>>(AH, AL, WH+4*DW, WL+4*DW, b1, 0, FH, FL, DD, FFD);
    gemm_hmma<0,0><<<gD, 256, SMEM>>>(FH, FL, WH+8*DW, WL+8*DW, b2, T0, 0, 0, FFD, DD);
    ln_add_kernel<<<ROWS, 128>>>(H1, T0, g2, be2, out);
}

// round 5
// speedup vs baseline: 2.4023x; 1.2646x over previous
#include <cuda_runtime.h>
#include <cuda_bf16.h>
#include <math.h>
#include <stdint.h>

#define BB 4
#define LL 2048
#define DD 512
#define HH 8
#define DK 64
#define FFD 2048
#define NTOP 40
#define SK 40
#define BH (BB*HH)
#define ROWS (BB*LL)
#define QS 1536          // fused QKV row stride

__device__ float g_QKV[ROWS*QS];
__device__ float g_ctx[ROWS*DD];
__device__ float g_h1[ROWS*DD];
__device__ float g_t0[ROWS*DD];
__device__ float g_M[BH*LL];
__device__ float g_vmean[BH*DK];
__device__ int   g_top[BH*NTOP];
__device__ float g_bcat[QS];
__device__ float g_sc[BH*NTOP*LL];
__device__ float g_mx[BH*NTOP];
__device__ float g_inv[BH*NTOP];
__device__ float g_part[4*BH*NTOP*DK];
__device__ __nv_bfloat16 g_Ahi[ROWS*DD];
__device__ __nv_bfloat16 g_Alo[ROWS*DD];
__device__ __nv_bfloat16 g_FFhi[ROWS*FFD];
__device__ __nv_bfloat16 g_FFlo[ROWS*FFD];
__device__ __nv_bfloat16 g_Whi[3*FFD*DD];
__device__ __nv_bfloat16 g_Wlo[3*FFD*DD];

__device__ __forceinline__ uint32_t smem_u32(const void* p){
    uint32_t a; asm("{ .reg .u64 t; cvta.to.shared.u64 t, %1; cvt.u32.u64 %0, t; }":"=r"(a):"l"(p)); return a;
}
__device__ __forceinline__ void cpasync16(uint32_t dst, const void* src){
    asm volatile("cp.async.cg.shared.global [%0], [%1], 16;" :: "r"(dst), "l"(src));
}
__device__ __forceinline__ void ldsm4(uint32_t* r, uint32_t addr){
    asm volatile("ldmatrix.sync.aligned.m8n8.x4.shared.b16 {%0,%1,%2,%3}, [%4];"
        : "=r"(r[0]),"=r"(r[1]),"=r"(r[2]),"=r"(r[3]) : "r"(addr));
}
__device__ __forceinline__ void mma_bf16(float* c, const uint32_t* a, const uint32_t* b){
    asm volatile("mma.sync.aligned.m16n8k16.row.col.f32.bf16.bf16.f32 "
        "{%0,%1,%2,%3}, {%4,%5,%6,%7}, {%8,%9}, {%0,%1,%2,%3};"
        : "+f"(c[0]),"+f"(c[1]),"+f"(c[2]),"+f"(c[3])
        : "r"(a[0]),"r"(a[1]),"r"(a[2]),"r"(a[3]),"r"(b[0]),"r"(b[1]));
}
__device__ __forceinline__ void split2(float v, __nv_bfloat16& h, __nv_bfloat16& l){
    h = __float2bfloat16(v);
    l = __float2bfloat16(v - __bfloat162float(h));
}

// =====================================================================
// HMMA GEMM (bf16 3-term split, fp32 acc). BM=BN=128, BK=32, 256 thr,
// 2 CTAs/SM. cp.async double buffer, 80B smem row stride.
// =====================================================================
template<int ACT, int SPLIT>
__global__ void __launch_bounds__(256,2)
gemm_hmma(const __nv_bfloat16* __restrict__ Ahi, const __nv_bfloat16* __restrict__ Alo,
          const __nv_bfloat16* __restrict__ Bhi, const __nv_bfloat16* __restrict__ Blo,
          const float* __restrict__ bias, float* __restrict__ C,
          __nv_bfloat16* __restrict__ Chi, __nv_bfloat16* __restrict__ Clo,
          int K, int ldc)
{
    extern __shared__ __align__(16) char sm[];
    const int t = threadIdx.x, lane = t&31, w = t>>5;
    const int wm = w>>2, wn = w&3;
    const int bm = blockIdx.y*128, bn = blockIdx.x*128;
    const int group = lane>>2, tig = lane&3;
    const uint32_t sbase = smem_u32(sm);

    float acc[4][4][4];
    #pragma unroll
    for (int i=0;i<4;i++)
        #pragma unroll
        for (int j=0;j<4;j++)
            #pragma unroll
            for (int r=0;r<4;r++) acc[i][j][r]=0.f;

    const __nv_bfloat16* srcs[4] = {Ahi, Alo, Bhi, Blo};
    const int nch = K>>5;
    {
        #pragma unroll
        for (int u=0; u<8; u++){
            int q = t + u*256;
            int tile = q>>9, rem = q&511;
            int r = rem>>2, c = rem&3;
            const __nv_bfloat16* src = srcs[tile] + (size_t)(((tile<2)?bm:bn) + r)*K + c*8;
            cpasync16(sbase + tile*10240 + r*80 + c*16, src);
        }
        asm volatile("cp.async.commit_group;");
    }
    for (int ch=0; ch<nch; ch++){
        asm volatile("cp.async.wait_group 0;");
        __syncthreads();
        if (ch+1 < nch){
            const int k0 = (ch+1)<<5;
            const uint32_t dst0 = sbase + ((ch+1)&1)*40960;
            #pragma unroll
            for (int u=0; u<8; u++){
                int q = t + u*256;
                int tile = q>>9, rem = q&511;
                int r = rem>>2, c = rem&3;
                const __nv_bfloat16* src = srcs[tile] + (size_t)(((tile<2)?bm:bn) + r)*K + k0 + c*8;
                cpasync16(dst0 + tile*10240 + r*80 + c*16, src);
            }
            asm volatile("cp.async.commit_group;");
        }
        const uint32_t stg = sbase + (ch&1)*40960;
        const char* stgp = sm + (ch&1)*40960;
        #pragma unroll
        for (int kk=0; kk<2; kk++){
            uint32_t a_h[4][4], a_l[4][4], b_h[4][2], b_l[4][2];
            #pragma unroll
            for (int mt=0; mt<4; mt++){
                uint32_t ra = stg + (uint32_t)((wm*64 + mt*16 + (lane&15))*80 + (lane>>4)*16 + kk*32);
                ldsm4(a_h[mt], ra);
                ldsm4(a_l[mt], ra + 10240u);
            }
            #pragma unroll
            for (int nt=0; nt<4; nt++){
                int off = 20480 + (wn*32 + nt*8 + group)*80 + tig*4 + kk*32;
                b_h[nt][0] = *(const uint32_t*)(stgp + off);
                b_h[nt][1] = *(const uint32_t*)(stgp + off + 16);
                b_l[nt][0] = *(const uint32_t*)(stgp + off + 10240);
                b_l[nt][1] = *(const uint32_t*)(stgp + off + 10240 + 16);
            }
            #pragma unroll
            for (int mt=0; mt<4; mt++)
                #pragma unroll
                for (int nt=0; nt<4; nt++){
                    mma_bf16(acc[mt][nt], a_h[mt], b_h[nt]);
                    mma_bf16(acc[mt][nt], a_h[mt], b_l[nt]);
                    mma_bf16(acc[mt][nt], a_l[mt], b_h[nt]);
                }
        }
    }
    __syncthreads();
    #pragma unroll
    for (int mt=0; mt<4; mt++){
        #pragma unroll
        for (int nt=0; nt<4; nt++){
            int r0  = bm + wm*64 + mt*16 + group;
            int col = bn + wn*32 + nt*8 + tig*2;
            float bb0 = bias[col], bb1 = bias[col+1];
            #pragma unroll
            for (int hh2=0; hh2<2; hh2++){
                int row = r0 + hh2*8;
                float v0 = acc[mt][nt][hh2*2+0] + bb0;
                float v1 = acc[mt][nt][hh2*2+1] + bb1;
                if (ACT==1){
                    v0 = 0.5f*v0*(1.0f + erff(v0*0.70710678118654752440f));
                    v1 = 0.5f*v1*(1.0f + erff(v1*0.70710678118654752440f));
                }
                if (SPLIT==0){
                    *(float2*)(C + (size_t)row*ldc + col) = make_float2(v0, v1);
                } else {
                    __nv_bfloat16 h0,h1,l0,l1;
                    split2(v0,h0,l0); split2(v1,h1,l1);
                    uint32_t hw = (uint32_t)__bfloat16_as_ushort(h0) | ((uint32_t)__bfloat16_as_ushort(h1)<<16);
                    uint32_t lw = (uint32_t)__bfloat16_as_ushort(l0) | ((uint32_t)__bfloat16_as_ushort(l1)<<16);
                    *(uint32_t*)(Chi + (size_t)row*ldc + col) = hw;
                    *(uint32_t*)(Clo + (size_t)row*ldc + col) = lw;
                }
            }
        }
    }
}

__global__ void convert_split(const float* __restrict__ src,
                              __nv_bfloat16* __restrict__ hi, __nv_bfloat16* __restrict__ lo, int n4)
{
    int i = blockIdx.x*256 + threadIdx.x;
    if (i>=n4) return;
    float4 v = ((const float4*)src)[i];
    __nv_bfloat16 h0,h1,h2,h3,l0,l1,l2,l3;
    split2(v.x,h0,l0); split2(v.y,h1,l1); split2(v.z,h2,l2); split2(v.w,h3,l3);
    uint2 hw, lw;
    hw.x=(uint32_t)__bfloat16_as_ushort(h0)|((uint32_t)__bfloat16_as_ushort(h1)<<16);
    hw.y=(uint32_t)__bfloat16_as_ushort(h2)|((uint32_t)__bfloat16_as_ushort(h3)<<16);
    lw.x=(uint32_t)__bfloat16_as_ushort(l0)|((uint32_t)__bfloat16_as_ushort(l1)<<16);
    lw.y=(uint32_t)__bfloat16_as_ushort(l2)|((uint32_t)__bfloat16_as_ushort(l3)<<16);
    ((uint2*)hi)[i]=hw; ((uint2*)lo)[i]=lw;
}

__global__ void bias_concat(const float* __restrict__ bq, const float* __restrict__ bk,
                            const float* __restrict__ bv)
{
    int t = blockIdx.x*256 + threadIdx.x;
    if (t>=QS) return;
    g_bcat[t] = (t<512)? bq[t] : (t<1024)? bk[t-512] : bv[t-1024];
}

__global__ void sample_scores_kernel(const int* __restrict__ idxs)
{
    int g = blockIdx.x*8 + (threadIdx.x>>5);
    int lane = threadIdx.x&31;
    int i = g&(LL-1), bh = g>>11, b = bh>>3, h = bh&7;
    const float* qp = g_QKV + (size_t)(b*LL+i)*QS + h*DK;
    float q0 = qp[lane], q1 = qp[32+lane];
    float mx = -INFINITY, sm = 0.f;
    #pragma unroll 4
    for (int j=0; j<SK; j++){
        int kidx = idxs[i*SK+j];
        const float* kp = g_QKV + (size_t)(b*LL+kidx)*QS + 512 + h*DK;
        float s = q0*kp[lane] + q1*kp[32+lane];
        #pragma unroll
        for (int off=16; off; off>>=1) s += __shfl_xor_sync(0xffffffffu, s, off);
        mx = fmaxf(mx, s); sm += s;
    }
    if (lane==0) g_M[bh*LL+i] = mx - sm*(1.0f/LL);
}

__global__ void topk_kernel()
{
    int bh = blockIdx.x, t = threadIdx.x;
    __shared__ float sv[LL];
    __shared__ float rv[256];
    __shared__ int ri[256];
    for (int l=t; l<LL; l+=256) sv[l] = g_M[bh*LL+l];
    __syncthreads();
    for (int it=0; it<NTOP; it++){
        float bv = -INFINITY; int bi = LL;
        for (int l=t; l<LL; l+=256){
            float v = sv[l];
            if (v>bv || (v==bv && l<bi)){ bv=v; bi=l; }
        }
        rv[t]=bv; ri[t]=bi; __syncthreads();
        for (int s=128; s; s>>=1){
            if (t<s && (rv[t+s]>rv[t] || (rv[t+s]==rv[t] && ri[t+s]<ri[t]))){ rv[t]=rv[t+s]; ri[t]=ri[t+s]; }
            __syncthreads();
        }
        if (t==0){ g_top[bh*NTOP+it]=ri[0]; sv[ri[0]]=-INFINITY; }
        __syncthreads();
    }
}

__global__ void vmean_kernel()
{
    int bh = blockIdx.x, b = bh>>3, h = bh&7;
    int t = threadIdx.x, d = t&63, r0 = t>>6;
    float s = 0.f;
    for (int l=r0; l<LL; l+=4) s += g_QKV[(size_t)(b*LL+l)*QS + 1024 + h*DK + d];
    __shared__ float red[256];
    red[t]=s; __syncthreads();
    if (t<64) g_vmean[bh*DK+t] = (red[t]+red[t+64]+red[t+128]+red[t+192])*(1.0f/LL);
}

__global__ void ctx_bcast_kernel()
{
    int idx = blockIdx.x*256 + threadIdx.x;
    int row = idx>>9, col = idx&511, b = row>>11, h = col>>6;
    g_ctx[idx] = g_vmean[(b*HH+h)*DK + (col&63)];
}

// scores for selected queries: grid (16 kt, 32 bh), block 128.
// Each thread owns one key-row, 40 query accumulators.
__global__ void attn_scores_kernel()
{
    int kt = blockIdx.x, bh = blockIdx.y, b = bh>>3, h = bh&7;
    int t = threadIdx.x;
    __shared__ float sq[NTOP][64];
    __shared__ __align__(16) float Ks[128][68];
    __shared__ int tops[NTOP];
    if (t < NTOP) tops[t] = g_top[bh*NTOP + t];
    __syncthreads();
    const size_t qkv = (size_t)b*LL*QS;
    for (int idx=t; idx<NTOP*64; idx+=128){
        int qn = idx>>6, d = idx&63;
        sq[qn][d] = g_QKV[qkv + (size_t)tops[qn]*QS + h*DK + d];
    }
    #pragma unroll
    for (int u=0; u<16; u++){
        int f = t + u*128;
        int r = f>>4, c = (f&15)<<2;
        float4 kv = *(const float4*)(&g_QKV[qkv + (size_t)(kt*128+r)*QS + 512 + h*DK + c]);
        *(float4*)(&Ks[r][c]) = kv;
    }
    __syncthreads();
    float acc[NTOP];
    #pragma unroll
    for (int qn=0; qn<NTOP; qn++) acc[qn]=0.f;
    for (int k2=0; k2<32; k2++){
        float2 kv = *(const float2*)(&Ks[t][k2*2]);
        #pragma unroll
        for (int qn=0; qn<NTOP; qn++){
            float2 qv = *(const float2*)(&sq[qn][k2*2]);
            acc[qn] += kv.x*qv.x + kv.y*qv.y;
        }
    }
    #pragma unroll
    for (int qn=0; qn<NTOP; qn++)
        g_sc[((size_t)bh*NTOP + qn)*LL + kt*128 + t] = acc[qn];
}

// per-row max and 1/sum(exp): grid 32 bh, block 256 (8 warps x 5 rows)
__global__ void attn_stats_kernel()
{
    int bh = blockIdx.x;
    int w = threadIdx.x>>5, lane = threadIdx.x&31;
    for (int j=0; j<5; j++){
        int qn = w*5 + j;
        const float* sp = g_sc + ((size_t)bh*NTOP + qn)*LL;
        float mx = -INFINITY;
        for (int i=lane; i<LL; i+=32) mx = fmaxf(mx, sp[i]);
        #pragma unroll
        for (int off=16; off; off>>=1) mx = fmaxf(mx, __shfl_xor_sync(0xffffffffu, mx, off));
        float sum = 0.f;
        for (int i=lane; i<LL; i+=32) sum += expf(sp[i]-mx);
        #pragma unroll
        for (int off=16; off; off>>=1) sum += __shfl_xor_sync(0xffffffffu, sum, off);
        if (lane==0){ g_mx[bh*NTOP+qn]=mx; g_inv[bh*NTOP+qn]=1.0f/sum; }
    }
}

// split-K PV partial: grid (4 ks, 32 bh), block 256. 55616B dynamic smem.
__global__ void attn_pv_kernel()
{
    extern __shared__ __align__(16) float psm[];
    float* Vs  = psm;            // 128*68
    float* P   = psm + 8704;     // 40*129
    float* smx = psm + 8704 + 5160;  // 40
    int ks = blockIdx.x, bh = blockIdx.y, b = bh>>3, h = bh&7;
    int t = threadIdx.x;
    if (t < NTOP) smx[t] = g_mx[bh*NTOP + t];
    __syncthreads();
    const size_t qkv = (size_t)b*LL*QS;
    int qg = t>>5, d2 = (t&31)*2;
    float acc[5][2];
    #pragma unroll
    for (int j=0;j<5;j++){ acc[j][0]=0.f; acc[j][1]=0.f; }
    for (int kt=0; kt<4; kt++){
        int ktg = ks*4 + kt;
        #pragma unroll
        for (int u=0; u<8; u++){
            int f = t + u*256;
            int r = f>>4, c = (f&15)<<2;
            float4 vv = *(const float4*)(&g_QKV[qkv + (size_t)(ktg*128+r)*QS + 1024 + h*DK + c]);
            *(float4*)(&Vs[r*68 + c]) = vv;
        }
        #pragma unroll
        for (int u=0; u<20; u++){
            int idx = t + u*256;
            int qn = idx>>7, row = idx&127;
            float s = g_sc[((size_t)bh*NTOP + qn)*LL + ktg*128 + row];
            P[qn*129 + row] = expf(s - smx[qn]);
        }
        __syncthreads();
        for (int row=0; row<128; row++){
            float2 vv = *(const float2*)(&Vs[row*68 + d2]);
            #pragma unroll
            for (int j=0; j<5; j++){
                float p = P[(qg*5+j)*129 + row];
                acc[j][0] += p*vv.x;
                acc[j][1] += p*vv.y;
            }
        }
        __syncthreads();
    }
    #pragma unroll
    for (int j=0; j<5; j++){
        int qn = qg*5 + j;
        float* dst = g_part + ((size_t)(ks*BH + bh)*NTOP + qn)*DK + d2;
        dst[0] = acc[j][0];
        dst[1] = acc[j][1];
    }
}

// combine partials, scale by inv, scatter to ctx: grid 32 bh, block 256
__global__ void attn_combine_kernel()
{
    int bh = blockIdx.x, b = bh>>3, h = bh&7;
    int t = threadIdx.x;
    __shared__ int tops[NTOP];
    __shared__ float sinv[NTOP];
    if (t < NTOP){ tops[t] = g_top[bh*NTOP+t]; sinv[t] = g_inv[bh*NTOP+t]; }
    __syncthreads();
    for (int e=t; e<NTOP*DK; e+=256){
        int qn = e>>6, d = e&63;
        float s = 0.f;
        #pragma unroll
        for (int ks=0; ks<4; ks++)
            s += g_part[((size_t)(ks*BH + bh)*NTOP + qn)*DK + d];
        g_ctx[(size_t)(b*LL + tops[qn])*DD + h*DK + d] = s * sinv[qn];
    }
}

__global__ void ln_add_kernel(const float* __restrict__ X, const float* __restrict__ Y,
                              const float* __restrict__ gg, const float* __restrict__ be,
                              float* __restrict__ out)
{
    int row = blockIdx.x, t = threadIdx.x;
    float4 a = ((const float4*)(X + (size_t)row*DD))[t];
    float4 bq = ((const float4*)(Y + (size_t)row*DD))[t];
    float4 v = make_float4(a.x+bq.x, a.y+bq.y, a.z+bq.z, a.w+bq.w);
    float s = v.x+v.y+v.z+v.w;
    float ss = v.x*v.x+v.y*v.y+v.z*v.z+v.w*v.w;
    __shared__ float rs[128], rq[128];
    rs[t]=s; rq[t]=ss; __syncthreads();
    for (int k=64; k; k>>=1){ if (t<k){ rs[t]+=rs[t+k]; rq[t]+=rq[t+k]; } __syncthreads(); }
    float mean = rs[0]*(1.0f/DD);
    float var  = rq[0]*(1.0f/DD) - mean*mean;
    float rstd = rsqrtf(var + 1e-5f);
    float4 g4 = ((const float4*)gg)[t], b4 = ((const float4*)be)[t];
    float4 o;
    o.x=(v.x-mean)*rstd*g4.x+b4.x; o.y=(v.y-mean)*rstd*g4.y+b4.y;
    o.z=(v.z-mean)*rstd*g4.z+b4.z; o.w=(v.w-mean)*rstd*g4.w+b4.w;
    ((float4*)(out + (size_t)row*DD))[t] = o;
}

extern "C" void kernel_launch(void* const* d_in, const int* in_sizes, int n_in,
                              void* d_out, int out_size)
{
    const float* x    = (const float*)d_in[0];
    const int*   idxs = (const int*)  d_in[1];
    const float* Wq = (const float*)d_in[2];  const float* bq = (const float*)d_in[3];
    const float* Wk = (const float*)d_in[4];  const float* bk = (const float*)d_in[5];
    const float* Wv = (const float*)d_in[6];  const float* bv = (const float*)d_in[7];
    const float* Wo = (const float*)d_in[8];  const float* bo = (const float*)d_in[9];
    const float* W1 = (const float*)d_in[10]; const float* b1 = (const float*)d_in[11];
    const float* W2 = (const float*)d_in[12]; const float* b2 = (const float*)d_in[13];
    const float* g1 = (const float*)d_in[14]; const float* be1 = (const float*)d_in[15];
    const float* g2 = (const float*)d_in[16]; const float* be2 = (const float*)d_in[17];
    float* out = (float*)d_out;

    float *QKV,*CTX,*H1,*T0,*BCAT;
    __nv_bfloat16 *AH,*AL,*FH,*FL,*WH,*WL;
    cudaGetSymbolAddress((void**)&QKV, g_QKV); cudaGetSymbolAddress((void**)&CTX, g_ctx);
    cudaGetSymbolAddress((void**)&H1, g_h1);   cudaGetSymbolAddress((void**)&T0, g_t0);
    cudaGetSymbolAddress((void**)&BCAT, g_bcat);
    cudaGetSymbolAddress((void**)&AH, g_Ahi);  cudaGetSymbolAddress((void**)&AL, g_Alo);
    cudaGetSymbolAddress((void**)&FH, g_FFhi); cudaGetSymbolAddress((void**)&FL, g_FFlo);
    cudaGetSymbolAddress((void**)&WH, g_Whi);  cudaGetSymbolAddress((void**)&WL, g_Wlo);

    const int SMEM = 81920;
    cudaFuncSetAttribute(gemm_hmma<0,0>, cudaFuncAttributeMaxDynamicSharedMemorySize, SMEM);
    cudaFuncSetAttribute(gemm_hmma<1,1>, cudaFuncAttributeMaxDynamicSharedMemorySize, SMEM);
    cudaFuncSetAttribute(attn_pv_kernel, cudaFuncAttributeMaxDynamicSharedMemorySize, 55616);

    const int DW = DD*DD;
    convert_split<<<DW/1024, 256>>>(Wq, WH+0*DW, WL+0*DW, DW/4);
    convert_split<<<DW/1024, 256>>>(Wk, WH+1*DW, WL+1*DW, DW/4);
    convert_split<<<DW/1024, 256>>>(Wv, WH+2*DW, WL+2*DW, DW/4);
    convert_split<<<DW/1024, 256>>>(Wo, WH+3*DW, WL+3*DW, DW/4);
    convert_split<<<DW*4/1024, 256>>>(W1, WH+4*DW, WL+4*DW, DW);
    convert_split<<<DW*4/1024, 256>>>(W2, WH+8*DW, WL+8*DW, DW);
    convert_split<<<ROWS*DD/1024, 256>>>(x, AH, AL, ROWS*DD/4);
    bias_concat<<<QS/256, 256>>>(bq, bk, bv);

    dim3 gQKV(QS/128, ROWS/128), gD(DD/128, ROWS/128), gF(FFD/128, ROWS/128);
    gemm_hmma<0,0><<<gQKV, 256, SMEM>>>(AH, AL, WH, WL, BCAT, QKV, 0, 0, DD, QS);

    sample_scores_kernel<<<ROWS*HH/8, 256>>>(idxs);
    topk_kernel<<<BH, 256>>>();
    vmean_kernel<<<BH, 256>>>();
    ctx_bcast_kernel<<<ROWS*DD/256, 256>>>();
    attn_scores_kernel<<<dim3(16, BH), 128>>>();
    attn_stats_kernel<<<BH, 256>>>();
    attn_pv_kernel<<<dim3(4, BH), 256, 55616>>>();
    attn_combine_kernel<<<BH, 256>>>();

    convert_split<<<ROWS*DD/1024, 256>>>(CTX, AH, AL, ROWS*DD/4);
    gemm_hmma<0,0><<<gD, 256, SMEM>>>(AH, AL, WH+3*DW, WL+3*DW, bo, T0, 0, 0, DD, DD);
    ln_add_kernel<<<ROWS, 128>>>(x, T0, g1, be1, H1);

    convert_split<<<ROWS*DD/1024, 256>>>(H1, AH, AL, ROWS*DD/4);
    gemm_hmma<1,1><<<gF, 256, SMEM>>>(AH, AL, WH+4*DW, WL+4*DW, b1, 0, FH, FL, DD, FFD);
    gemm_hmma<0,0><<<gD, 256, SMEM>>>(FH, FL, WH+8*DW, WL+8*DW, b2, T0, 0, 0, FFD, DD);
    ln_add_kernel<<<ROWS, 128>>>(H1, T0, g2, be2, out);
}

// round 7
// speedup vs baseline: 2.6257x; 1.0930x over previous
#include <cuda_runtime.h>
#include <cuda_bf16.h>
#include <math.h>
#include <stdint.h>

#define BB 4
#define LL 2048
#define DD 512
#define HH 8
#define DK 64
#define FFD 2048
#define NTOP 40
#define SK 40
#define BH (BB*HH)
#define ROWS (BB*LL)
#define QS 1536

__device__ float g_QKV[ROWS*QS];
__device__ float g_h1[ROWS*DD];
__device__ float g_t0[ROWS*DD];
__device__ float g_M[BH*LL];
__device__ float g_vmean[BH*DK];
__device__ int   g_top[BH*NTOP];
__device__ float g_bcat[QS];
__device__ float g_sc[BH*NTOP*LL];
__device__ float g_mx[BH*NTOP];
__device__ float g_inv[BH*NTOP];
__device__ float g_part[4*BH*NTOP*DK];
__device__ __nv_bfloat16 g_Ahi[ROWS*DD];
__device__ __nv_bfloat16 g_Alo[ROWS*DD];
__device__ __nv_bfloat16 g_FFhi[ROWS*FFD];
__device__ __nv_bfloat16 g_FFlo[ROWS*FFD];
__device__ __nv_bfloat16 g_Whi[3*FFD*DD];
__device__ __nv_bfloat16 g_Wlo[3*FFD*DD];

__device__ __forceinline__ uint32_t smem_u32(const void* p){
    uint32_t a; asm("{ .reg .u64 t; cvta.to.shared.u64 t, %1; cvt.u32.u64 %0, t; }":"=r"(a):"l"(p)); return a;
}
__device__ __forceinline__ void cpasync16(uint32_t dst, const void* src){
    asm volatile("cp.async.cg.shared.global [%0], [%1], 16;" :: "r"(dst), "l"(src));
}
__device__ __forceinline__ void ldsm4(uint32_t* r, uint32_t addr){
    asm volatile("ldmatrix.sync.aligned.m8n8.x4.shared.b16 {%0,%1,%2,%3}, [%4];"
        : "=r"(r[0]),"=r"(r[1]),"=r"(r[2]),"=r"(r[3]) : "r"(addr));
}
__device__ __forceinline__ void mma_bf16(float* c, const uint32_t* a, const uint32_t* b){
    asm volatile("mma.sync.aligned.m16n8k16.row.col.f32.bf16.bf16.f32 "
        "{%0,%1,%2,%3}, {%4,%5,%6,%7}, {%8,%9}, {%0,%1,%2,%3};"
        : "+f"(c[0]),"+f"(c[1]),"+f"(c[2]),"+f"(c[3])
        : "r"(a[0]),"r"(a[1]),"r"(a[2]),"r"(a[3]),"r"(b[0]),"r"(b[1]));
}
__device__ __forceinline__ void split2(float v, __nv_bfloat16& h, __nv_bfloat16& l){
    h = __float2bfloat16(v);
    l = __float2bfloat16(v - __bfloat162float(h));
}
__device__ __forceinline__ uint32_t packbf(__nv_bfloat16 a, __nv_bfloat16 b){
    return (uint32_t)__bfloat16_as_ushort(a) | ((uint32_t)__bfloat16_as_ushort(b)<<16);
}

// =====================================================================
// HMMA GEMM (bf16 3-term split, fp32 acc). BM=BN=128, BK=32, 256 thr,
// 2 CTAs/SM. B-fragments loaded per-nt to keep regs < 128 (no spill).
// cp.async for stage ch+1 issued BEFORE waiting on stage ch (wait_group 1).
// =====================================================================
template<int ACT, int SPLIT>
__global__ void __launch_bounds__(256,2)
gemm_hmma(const __nv_bfloat16* __restrict__ Ahi, const __nv_bfloat16* __restrict__ Alo,
          const __nv_bfloat16* __restrict__ Bhi, const __nv_bfloat16* __restrict__ Blo,
          const float* __restrict__ bias, float* __restrict__ C,
          __nv_bfloat16* __restrict__ Chi, __nv_bfloat16* __restrict__ Clo,
          int K, int ldc)
{
    extern __shared__ __align__(16) char sm[];
    const int t = threadIdx.x, lane = t&31, w = t>>5;
    const int wm = w>>2, wn = w&3;
    const int bm = blockIdx.y*128, bn = blockIdx.x*128;
    const int group = lane>>2, tig = lane&3;
    const uint32_t sbase = smem_u32(sm);

    float acc[4][4][4];
    #pragma unroll
    for (int i=0;i<4;i++)
        #pragma unroll
        for (int j=0;j<4;j++)
            #pragma unroll
            for (int r=0;r<4;r++) acc[i][j][r]=0.f;

    const __nv_bfloat16* srcs[4] = {Ahi, Alo, Bhi, Blo};
    const int nch = K>>5;
    {
        #pragma unroll
        for (int u=0; u<8; u++){
            int q = t + u*256;
            int tile = q>>9, rem = q&511;
            int r = rem>>2, c = rem&3;
            const __nv_bfloat16* src = srcs[tile] + (size_t)(((tile<2)?bm:bn) + r)*K + c*8;
            cpasync16(sbase + tile*10240 + r*80 + c*16, src);
        }
        asm volatile("cp.async.commit_group;");
    }
    for (int ch=0; ch<nch; ch++){
        if (ch+1 < nch){
            const int k0 = (ch+1)<<5;
            const uint32_t dst0 = sbase + ((ch+1)&1)*40960;
            #pragma unroll
            for (int u=0; u<8; u++){
                int q = t + u*256;
                int tile = q>>9, rem = q&511;
                int r = rem>>2, c = rem&3;
                const __nv_bfloat16* src = srcs[tile] + (size_t)(((tile<2)?bm:bn) + r)*K + k0 + c*8;
                cpasync16(dst0 + tile*10240 + r*80 + c*16, src);
            }
            asm volatile("cp.async.commit_group;");
            asm volatile("cp.async.wait_group 1;");
        } else {
            asm volatile("cp.async.wait_group 0;");
        }
        __syncthreads();
        const uint32_t stg = sbase + (ch&1)*40960;
        const char* stgp = sm + (ch&1)*40960;
        #pragma unroll
        for (int kk=0; kk<2; kk++){
            uint32_t a_h[4][4], a_l[4][4];
            #pragma unroll
            for (int mt=0; mt<4; mt++){
                uint32_t ra = stg + (uint32_t)((wm*64 + mt*16 + (lane&15))*80 + (lane>>4)*16 + kk*32);
                ldsm4(a_h[mt], ra);
                ldsm4(a_l[mt], ra + 10240u);
            }
            #pragma unroll
            for (int nt=0; nt<4; nt++){
                uint32_t b_h[2], b_l[2];
                int off = 20480 + (wn*32 + nt*8 + group)*80 + tig*4 + kk*32;
                b_h[0] = *(const uint32_t*)(stgp + off);
                b_h[1] = *(const uint32_t*)(stgp + off + 16);
                b_l[0] = *(const uint32_t*)(stgp + off + 10240);
                b_l[1] = *(const uint32_t*)(stgp + off + 10240 + 16);
                #pragma unroll
                for (int mt=0; mt<4; mt++){
                    mma_bf16(acc[mt][nt], a_h[mt], b_h);
                    mma_bf16(acc[mt][nt], a_h[mt], b_l);
                    mma_bf16(acc[mt][nt], a_l[mt], b_h);
                }
            }
        }
        __syncthreads();
    }
    #pragma unroll
    for (int mt=0; mt<4; mt++){
        #pragma unroll
        for (int nt=0; nt<4; nt++){
            int r0  = bm + wm*64 + mt*16 + group;
            int col = bn + wn*32 + nt*8 + tig*2;
            float bb0 = bias[col], bb1 = bias[col+1];
            #pragma unroll
            for (int hh2=0; hh2<2; hh2++){
                int row = r0 + hh2*8;
                float v0 = acc[mt][nt][hh2*2+0] + bb0;
                float v1 = acc[mt][nt][hh2*2+1] + bb1;
                if (ACT==1){
                    v0 = 0.5f*v0*(1.0f + erff(v0*0.70710678118654752440f));
                    v1 = 0.5f*v1*(1.0f + erff(v1*0.70710678118654752440f));
                }
                if (SPLIT==0){
                    *(float2*)(C + (size_t)row*ldc + col) = make_float2(v0, v1);
                } else {
                    __nv_bfloat16 h0,h1,l0,l1;
                    split2(v0,h0,l0); split2(v1,h1,l1);
                    *(uint32_t*)(Chi + (size_t)row*ldc + col) = packbf(h0,h1);
                    *(uint32_t*)(Clo + (size_t)row*ldc + col) = packbf(l0,l1);
                }
            }
        }
    }
}

__global__ void convert_split(const float* __restrict__ src,
                              __nv_bfloat16* __restrict__ hi, __nv_bfloat16* __restrict__ lo, int n4)
{
    int i = blockIdx.x*256 + threadIdx.x;
    if (i>=n4) return;
    float4 v = ((const float4*)src)[i];
    __nv_bfloat16 h0,h1,h2,h3,l0,l1,l2,l3;
    split2(v.x,h0,l0); split2(v.y,h1,l1); split2(v.z,h2,l2); split2(v.w,h3,l3);
    uint2 hw = make_uint2(packbf(h0,h1), packbf(h2,h3));
    uint2 lw = make_uint2(packbf(l0,l1), packbf(l2,l3));
    ((uint2*)hi)[i]=hw; ((uint2*)lo)[i]=lw;
}

__global__ void bias_concat(const float* __restrict__ bq, const float* __restrict__ bk,
                            const float* __restrict__ bv)
{
    int t = blockIdx.x*256 + threadIdx.x;
    if (t>=QS) return;
    g_bcat[t] = (t<512)? bq[t] : (t<1024)? bk[t-512] : bv[t-1024];
}

// one warp per (bh,i): idx broadcast from regs, float2 loads
__global__ void sample_scores_kernel(const int* __restrict__ idxs)
{
    int g = blockIdx.x*8 + (threadIdx.x>>5);
    int lane = threadIdx.x&31;
    int i = g&(LL-1), bh = g>>11, b = bh>>3, h = bh&7;
    const float2* qp = (const float2*)(g_QKV + (size_t)(b*LL+i)*QS + h*DK);
    float2 q = qp[lane];
    int myi0 = idxs[i*SK + lane];
    int myi1 = (lane<8)? idxs[i*SK + 32 + lane] : 0;
    const float* kbase = g_QKV + (size_t)b*LL*QS + 512 + h*DK;
    float mx = -INFINITY, sm = 0.f;
    #pragma unroll 4
    for (int j=0; j<SK; j++){
        int kidx = (j<32)? __shfl_sync(0xffffffffu, myi0, j)
                         : __shfl_sync(0xffffffffu, myi1, j-32);
        float2 kv = ((const float2*)(kbase + (size_t)kidx*QS))[lane];
        float s = q.x*kv.x + q.y*kv.y;
        #pragma unroll
        for (int off=16; off; off>>=1) s += __shfl_xor_sync(0xffffffffu, s, off);
        mx = fmaxf(mx, s); sm += s;
    }
    if (lane==0) g_M[bh*LL+i] = mx - sm*(1.0f/LL);
}

// =====================================================================
// top-40 via MSB-first radix select. Ties -> lowest index (jax top_k).
// =====================================================================
__global__ void topk_kernel()
{
    int bh = blockIdx.x, t = threadIdx.x;   // 256 threads
    __shared__ uint32_t su[LL];
    __shared__ int hist[256];
    __shared__ int s_bucket, s_taken;
    __shared__ int tsum[256];
    __shared__ int s_ctr;

    for (int l=t; l<LL; l+=256){
        uint32_t s = __float_as_uint(g_M[bh*LL+l]);
        su[l] = (s & 0x80000000u)? ~s : (s | 0x80000000u);
    }
    if (t==0) s_ctr = 0;
    __syncthreads();

    uint32_t prefix = 0;
    int remaining = NTOP;
    #pragma unroll
    for (int round=0; round<4; round++){
        int shift = 24 - round*8;
        hist[t] = 0;
        __syncthreads();
        for (int l=t; l<LL; l+=256){
            uint32_t u = su[l];
            bool m = (round==0) || (((u ^ prefix) >> (shift+8)) == 0u);
            if (m) atomicAdd(&hist[(u>>shift)&255], 1);
        }
        __syncthreads();
        if (t < 32){
            // lane t owns buckets 255-8t .. 255-8t-7 (descending order)
            int loc[8], run = 0;
            #pragma unroll
            for (int k=0; k<8; k++){
                int b = 255 - (t*8 + k);
                loc[k] = run;
                run += hist[b];
            }
            int lane_total = run;
            int scan = lane_total;                 // Hillis-Steele inclusive scan
            #pragma unroll
            for (int off=1; off<32; off<<=1){
                int v = __shfl_up_sync(0xffffffffu, scan, off);
                if (t >= off) scan += v;
            }
            int excl = scan - lane_total;          // sum over lanes < t
            #pragma unroll
            for (int k=0; k<8; k++){
                int b = 255 - (t*8 + k);
                int cumAbove = excl + loc[k];
                if (cumAbove < remaining && remaining <= cumAbove + hist[b]){
                    s_bucket = b;
                    s_taken  = cumAbove;
                }
            }
        }
        __syncthreads();
        prefix |= ((uint32_t)s_bucket) << shift;
        remaining -= s_taken;
        __syncthreads();
    }
    const uint32_t T = prefix;     // exact 40th-largest pattern
    const int r = remaining;       // # ties of T to take (lowest index first)
    const int cnt_gt = NTOP - r;

    int base = t*8, c = 0;
    #pragma unroll
    for (int k=0; k<8; k++) if (su[base+k] == T) c++;
    tsum[t] = c;
    __syncthreads();
    for (int off=1; off<256; off<<=1){
        int v = (t>=off)? tsum[t-off] : 0;
        __syncthreads();
        tsum[t] += v;
        __syncthreads();
    }
    int excl = tsum[t] - c;
    #pragma unroll
    for (int k=0; k<8; k++){
        uint32_t u = su[base+k];
        if (u > T){
            int pos = atomicAdd(&s_ctr, 1);
            g_top[bh*NTOP + pos] = base + k;
        } else if (u == T){
            if (excl < r) g_top[bh*NTOP + cnt_gt + excl] = base + k;
            excl++;
        }
    }
}

__global__ void vmean_kernel()
{
    int bh = blockIdx.x, b = bh>>3, h = bh&7;
    int t = threadIdx.x, d = t&63, r0 = t>>6;
    float s = 0.f;
    for (int l=r0; l<LL; l+=4) s += g_QKV[(size_t)(b*LL+l)*QS + 1024 + h*DK + d];
    __shared__ float red[256];
    red[t]=s; __syncthreads();
    if (t<64) g_vmean[bh*DK+t] = (red[t]+red[t+64]+red[t+128]+red[t+192])*(1.0f/LL);
}

// broadcast vmean directly as bf16 hi/lo splits (2 cols per thread)
__global__ void ctx_bcast_kernel(__nv_bfloat16* __restrict__ hi, __nv_bfloat16* __restrict__ lo)
{
    int i = blockIdx.x*256 + threadIdx.x;       // over ROWS*DD/2
    int row = i>>8, c2 = (i&255)*2;
    int b = row>>11, h = c2>>6;
    const float* vm = g_vmean + (b*HH+h)*DK;
    float v0 = vm[c2&63], v1 = vm[(c2&63)+1];
    __nv_bfloat16 h0,h1,l0,l1;
    split2(v0,h0,l0); split2(v1,h1,l1);
    *(uint32_t*)(hi + (size_t)row*DD + c2) = packbf(h0,h1);
    *(uint32_t*)(lo + (size_t)row*DD + c2) = packbf(l0,l1);
}

__global__ void attn_scores_kernel()
{
    int kt = blockIdx.x, bh = blockIdx.y, b = bh>>3, h = bh&7;
    int t = threadIdx.x;
    __shared__ float sq[NTOP][64];
    __shared__ __align__(16) float Ks[128][68];
    __shared__ int tops[NTOP];
    if (t < NTOP) tops[t] = g_top[bh*NTOP + t];
    __syncthreads();
    const size_t qkv = (size_t)b*LL*QS;
    for (int idx=t; idx<NTOP*64; idx+=128){
        int qn = idx>>6, d = idx&63;
        sq[qn][d] = g_QKV[qkv + (size_t)tops[qn]*QS + h*DK + d];
    }
    #pragma unroll
    for (int u=0; u<16; u++){
        int f = t + u*128;
        int r = f>>4, c = (f&15)<<2;
        float4 kv = *(const float4*)(&g_QKV[qkv + (size_t)(kt*128+r)*QS + 512 + h*DK + c]);
        *(float4*)(&Ks[r][c]) = kv;
    }
    __syncthreads();
    float acc[NTOP];
    #pragma unroll
    for (int qn=0; qn<NTOP; qn++) acc[qn]=0.f;
    for (int k2=0; k2<32; k2++){
        float2 kv = *(const float2*)(&Ks[t][k2*2]);
        #pragma unroll
        for (int qn=0; qn<NTOP; qn++){
            float2 qv = *(const float2*)(&sq[qn][k2*2]);
            acc[qn] += kv.x*qv.x + kv.y*qv.y;
        }
    }
    #pragma unroll
    for (int qn=0; qn<NTOP; qn++)
        g_sc[((size_t)bh*NTOP + qn)*LL + kt*128 + t] = acc[qn];
}

__global__ void attn_stats_kernel()
{
    int bh = blockIdx.x;
    int w = threadIdx.x>>5, lane = threadIdx.x&31;
    for (int j=0; j<5; j++){
        int qn = w*5 + j;
        const float* sp = g_sc + ((size_t)bh*NTOP + qn)*LL;
        float mx = -INFINITY;
        for (int i=lane; i<LL; i+=32) mx = fmaxf(mx, sp[i]);
        #pragma unroll
        for (int off=16; off; off>>=1) mx = fmaxf(mx, __shfl_xor_sync(0xffffffffu, mx, off));
        float sum = 0.f;
        for (int i=lane; i<LL; i+=32) sum += expf(sp[i]-mx);
        #pragma unroll
        for (int off=16; off; off>>=1) sum += __shfl_xor_sync(0xffffffffu, sum, off);
        if (lane==0){ g_mx[bh*NTOP+qn]=mx; g_inv[bh*NTOP+qn]=1.0f/sum; }
    }
}

__global__ void attn_pv_kernel()
{
    extern __shared__ __align__(16) float psm[];
    float* Vs  = psm;
    float* P   = psm + 8704;
    float* smx = psm + 8704 + 5160;
    int ks = blockIdx.x, bh = blockIdx.y, b = bh>>3, h = bh&7;
    int t = threadIdx.x;
    if (t < NTOP) smx[t] = g_mx[bh*NTOP + t];
    __syncthreads();
    const size_t qkv = (size_t)b*LL*QS;
    int qg = t>>5, d2 = (t&31)*2;
    float acc[5][2];
    #pragma unroll
    for (int j=0;j<5;j++){ acc[j][0]=0.f; acc[j][1]=0.f; }
    for (int kt=0; kt<4; kt++){
        int ktg = ks*4 + kt;
        #pragma unroll
        for (int u=0; u<8; u++){
            int f = t + u*256;
            int r = f>>4, c = (f&15)<<2;
            float4 vv = *(const float4*)(&g_QKV[qkv + (size_t)(ktg*128+r)*QS + 1024 + h*DK + c]);
            *(float4*)(&Vs[r*68 + c]) = vv;
        }
        #pragma unroll
        for (int u=0; u<20; u++){
            int idx = t + u*256;
            int qn = idx>>7, row = idx&127;
            float s = g_sc[((size_t)bh*NTOP + qn)*LL + ktg*128 + row];
            P[qn*129 + row] = expf(s - smx[qn]);
        }
        __syncthreads();
        for (int row=0; row<128; row++){
            float2 vv = *(const float2*)(&Vs[row*68 + d2]);
            #pragma unroll
            for (int j=0; j<5; j++){
                float p = P[(qg*5+j)*129 + row];
                acc[j][0] += p*vv.x;
                acc[j][1] += p*vv.y;
            }
        }
        __syncthreads();
    }
    #pragma unroll
    for (int j=0; j<5; j++){
        int qn = qg*5 + j;
        float* dst = g_part + ((size_t)(ks*BH + bh)*NTOP + qn)*DK + d2;
        dst[0] = acc[j][0];
        dst[1] = acc[j][1];
    }
}

// combine partials -> bf16 hi/lo splits of ctx rows
__global__ void attn_combine_kernel(__nv_bfloat16* __restrict__ hi, __nv_bfloat16* __restrict__ lo)
{
    int bh = blockIdx.x, b = bh>>3, h = bh&7;
    int t = threadIdx.x;
    __shared__ int tops[NTOP];
    __shared__ float sinv[NTOP];
    if (t < NTOP){ tops[t] = g_top[bh*NTOP+t]; sinv[t] = g_inv[bh*NTOP+t]; }
    __syncthreads();
    for (int e=t; e<NTOP*DK/2; e+=256){
        int qn = e>>5, d2 = (e&31)*2;
        float s0=0.f, s1=0.f;
        #pragma unroll
        for (int ks=0; ks<4; ks++){
            const float* pp = g_part + ((size_t)(ks*BH + bh)*NTOP + qn)*DK + d2;
            s0 += pp[0]; s1 += pp[1];
        }
        s0 *= sinv[qn]; s1 *= sinv[qn];
        size_t o = (size_t)(b*LL + tops[qn])*DD + h*DK + d2;
        __nv_bfloat16 h0,h1,l0,l1;
        split2(s0,h0,l0); split2(s1,h1,l1);
        *(uint32_t*)(hi + o) = packbf(h0,h1);
        *(uint32_t*)(lo + o) = packbf(l0,l1);
    }
}

// LN(X+Y): SPLITOUT=1 also emits bf16 hi/lo of the result
template<int SPLITOUT>
__global__ void ln_add_kernel(const float* __restrict__ X, const float* __restrict__ Y,
                              const float* __restrict__ gg, const float* __restrict__ be,
                              float* __restrict__ out,
                              __nv_bfloat16* __restrict__ hi, __nv_bfloat16* __restrict__ lo)
{
    int row = blockIdx.x, t = threadIdx.x;
    float4 a = ((const float4*)(X + (size_t)row*DD))[t];
    float4 bq = ((const float4*)(Y + (size_t)row*DD))[t];
    float4 v = make_float4(a.x+bq.x, a.y+bq.y, a.z+bq.z, a.w+bq.w);
    float s = v.x+v.y+v.z+v.w;
    float ss = v.x*v.x+v.y*v.y+v.z*v.z+v.w*v.w;
    __shared__ float rs[128], rq[128];
    rs[t]=s; rq[t]=ss; __syncthreads();
    for (int k=64; k; k>>=1){ if (t<k){ rs[t]+=rs[t+k]; rq[t]+=rq[t+k]; } __syncthreads(); }
    float mean = rs[0]*(1.0f/DD);
    float var  = rq[0]*(1.0f/DD) - mean*mean;
    float rstd = rsqrtf(var + 1e-5f);
    float4 g4 = ((const float4*)gg)[t], b4 = ((const float4*)be)[t];
    float4 o;
    o.x=(v.x-mean)*rstd*g4.x+b4.x; o.y=(v.y-mean)*rstd*g4.y+b4.y;
    o.z=(v.z-mean)*rstd*g4.z+b4.z; o.w=(v.w-mean)*rstd*g4.w+b4.w;
    ((float4*)(out + (size_t)row*DD))[t] = o;
    if (SPLITOUT){
        __nv_bfloat16 h0,h1,h2,h3,l0,l1,l2,l3;
        split2(o.x,h0,l0); split2(o.y,h1,l1); split2(o.z,h2,l2); split2(o.w,h3,l3);
        uint2 hw = make_uint2(packbf(h0,h1), packbf(h2,h3));
        uint2 lw = make_uint2(packbf(l0,l1), packbf(l2,l3));
        ((uint2*)(hi + (size_t)row*DD))[t] = hw;
        ((uint2*)(lo + (size_t)row*DD))[t] = lw;
    }
}

extern "C" void kernel_launch(void* const* d_in, const int* in_sizes, int n_in,
                              void* d_out, int out_size)
{
    const float* x    = (const float*)d_in[0];
    const int*   idxs = (const int*)  d_in[1];
    const float* Wq = (const float*)d_in[2];  const float* bq = (const float*)d_in[3];
    const float* Wk = (const float*)d_in[4];  const float* bk = (const float*)d_in[5];
    const float* Wv = (const float*)d_in[6];  const float* bv = (const float*)d_in[7];
    const float* Wo = (const float*)d_in[8];  const float* bo = (const float*)d_in[9];
    const float* W1 = (const float*)d_in[10]; const float* b1 = (const float*)d_in[11];
    const float* W2 = (const float*)d_in[12]; const float* b2 = (const float*)d_in[13];
    const float* g1 = (const float*)d_in[14]; const float* be1 = (const float*)d_in[15];
    const float* g2 = (const float*)d_in[16]; const float* be2 = (const float*)d_in[17];
    float* out = (float*)d_out;

    float *QKV,*H1,*T0,*BCAT;
    __nv_bfloat16 *AH,*AL,*FH,*FL,*WH,*WL;
    cudaGetSymbolAddress((void**)&QKV, g_QKV);
    cudaGetSymbolAddress((void**)&H1, g_h1);   cudaGetSymbolAddress((void**)&T0, g_t0);
    cudaGetSymbolAddress((void**)&BCAT, g_bcat);
    cudaGetSymbolAddress((void**)&AH, g_Ahi);  cudaGetSymbolAddress((void**)&AL, g_Alo);
    cudaGetSymbolAddress((void**)&FH, g_FFhi); cudaGetSymbolAddress((void**)&FL, g_FFlo);
    cudaGetSymbolAddress((void**)&WH, g_Whi);  cudaGetSymbolAddress((void**)&WL, g_Wlo);

    const int SMEM = 81920;
    cudaFuncSetAttribute(gemm_hmma<0,0>, cudaFuncAttributeMaxDynamicSharedMemorySize, SMEM);
    cudaFuncSetAttribute(gemm_hmma<1,1>, cudaFuncAttributeMaxDynamicSharedMemorySize, SMEM);
    cudaFuncSetAttribute(attn_pv_kernel, cudaFuncAttributeMaxDynamicSharedMemorySize, 55616);

    const int DW = DD*DD;
    convert_split<<<DW/1024, 256>>>(Wq, WH+0*DW, WL+0*DW, DW/4);
    convert_split<<<DW/1024, 256>>>(Wk, WH+1*DW, WL+1*DW, DW/4);
    convert_split<<<DW/1024, 256>>>(Wv, WH+2*DW, WL+2*DW, DW/4);
    convert_split<<<DW/1024, 256>>>(Wo, WH+3*DW, WL+3*DW, DW/4);
    convert_split<<<DW*4/1024, 256>>>(W1, WH+4*DW, WL+4*DW, DW);
    convert_split<<<DW*4/1024, 256>>>(W2, WH+8*DW, WL+8*DW, DW);
    convert_split<<<ROWS*DD/1024, 256>>>(x, AH, AL, ROWS*DD/4);
    bias_concat<<<QS/256, 256>>>(bq, bk, bv);

    dim3 gQKV(QS/128, ROWS/128), gD(DD/128, ROWS/128), gF(FFD/128, ROWS/128);
    gemm_hmma<0,0><<<gQKV, 256, SMEM>>>(AH, AL, WH, WL, BCAT, QKV, 0, 0, DD, QS);

    sample_scores_kernel<<<ROWS*HH/8, 256>>>(idxs);
    topk_kernel<<<BH, 256>>>();
    vmean_kernel<<<BH, 256>>>();
    ctx_bcast_kernel<<<ROWS*DD/512, 256>>>(AH, AL);
    attn_scores_kernel<<<dim3(16, BH), 128>>>();
    attn_stats_kernel<<<BH, 256>>>();
    attn_pv_kernel<<<dim3(4, BH), 256, 55616>>>();
    attn_combine_kernel<<<BH, 256>>>(AH, AL);

    gemm_hmma<0,0><<<gD, 256, SMEM>>>(AH, AL, WH+3*DW, WL+3*DW, bo, T0, 0, 0, DD, DD);
    ln_add_kernel<1><<<ROWS, 128>>>(x, T0, g1, be1, H1, AH, AL);

    gemm_hmma<1,1><<<gF, 256, SMEM>>>(AH, AL, WH+4*DW, WL+4*DW, b1, 0, FH, FL, DD, FFD);
    gemm_hmma<0,0><<<gD, 256, SMEM>>>(FH, FL, WH+8*DW, WL+8*DW, b2, T0, 0, 0, FFD, DD);
    ln_add_kernel<0><<<ROWS, 128>>>(H1, T0, g2, be2, out, 0, 0);
}